// round 3
// baseline (speedup 1.0000x reference)
#include <cuda_runtime.h>
#include <cuda_bf16.h>

#define N_NODES 100000
#define N_EDGES 1250000
#define D_IN 64
#define D_HID 32
#define D_OUT 41

#define SCAN_BLK 1024
#define SCAN_ITEMS 4
#define SCAN_CHUNK (SCAN_BLK * SCAN_ITEMS)          // 4096
#define SCAN_NBLK ((N_NODES + SCAN_CHUNK - 1) / SCAN_CHUNK)  // 25

// ---------------- device scratch (static: no runtime allocation) ------------
__device__ __align__(16) int   g_cnt[N_NODES];
__device__ __align__(16) int   g_rowptr[N_NODES + 4];
__device__ __align__(16) int   g_cursor[N_NODES];
__device__ __align__(16) int   g_csr_src[N_EDGES];
__device__ __align__(16) int   g_blocksums[SCAN_NBLK + 3];
__device__ __align__(16) float g_y1l[N_NODES * D_HID];   // x @ W1l
__device__ __align__(16) float g_y1r[N_NODES * D_HID];   // x @ W1r + b1
__device__ __align__(16) float g_h  [N_NODES * D_HID];   // layer-1 output (post relu)
__device__ __align__(16) float g_agg2[N_NODES * D_HID];  // mean-agg of h

// ---------------- CSR build --------------------------------------------------
__global__ void k_zero_cnt() {
    int i = blockIdx.x * blockDim.x + threadIdx.x;
    if (i < N_NODES) g_cnt[i] = 0;
}

// edge_index is int32 [2, E] (JAX x64 disabled: int64 request silently -> int32)
__global__ void k_histogram(const int* __restrict__ ei) {
    int e = blockIdx.x * blockDim.x + threadIdx.x;
    if (e < N_EDGES) {
        int d = ei[N_EDGES + e];
        if ((unsigned)d < (unsigned)N_NODES) atomicAdd(&g_cnt[d], 1);
    }
}

__global__ void k_scan_a() {
    __shared__ int sh[SCAN_BLK];
    int base = blockIdx.x * SCAN_CHUNK;
    int t = threadIdx.x;
    int s = 0;
#pragma unroll
    for (int i = 0; i < SCAN_ITEMS; i++) {
        int idx = base + t * SCAN_ITEMS + i;
        if (idx < N_NODES) s += g_cnt[idx];
    }
    sh[t] = s;
    __syncthreads();
    for (int off = SCAN_BLK / 2; off > 0; off >>= 1) {
        if (t < off) sh[t] += sh[t + off];
        __syncthreads();
    }
    if (t == 0) g_blocksums[blockIdx.x] = sh[0];
}

__global__ void k_scan_b() {
    if (threadIdx.x == 0 && blockIdx.x == 0) {
        int run = 0;
        for (int b = 0; b < SCAN_NBLK; b++) {
            int v = g_blocksums[b];
            g_blocksums[b] = run;
            run += v;
        }
    }
}

__global__ void k_scan_c() {
    __shared__ int sh[SCAN_BLK];
    int base = blockIdx.x * SCAN_CHUNK;
    int t = threadIdx.x;
    int v[SCAN_ITEMS];
    int s = 0;
#pragma unroll
    for (int i = 0; i < SCAN_ITEMS; i++) {
        int idx = base + t * SCAN_ITEMS + i;
        v[i] = (idx < N_NODES) ? g_cnt[idx] : 0;
        s += v[i];
    }
    sh[t] = s;
    __syncthreads();
    // Hillis-Steele inclusive scan over per-thread sums
    for (int off = 1; off < SCAN_BLK; off <<= 1) {
        int x = (t >= off) ? sh[t - off] : 0;
        __syncthreads();
        sh[t] += x;
        __syncthreads();
    }
    int run = ((t > 0) ? sh[t - 1] : 0) + g_blocksums[blockIdx.x];
#pragma unroll
    for (int i = 0; i < SCAN_ITEMS; i++) {
        int idx = base + t * SCAN_ITEMS + i;
        if (idx < N_NODES) {
            g_rowptr[idx] = run;
            g_cursor[idx] = run;
        }
        run += v[i];
    }
    if (blockIdx.x == 0 && t == 0) g_rowptr[N_NODES] = N_EDGES;
}

__global__ void k_scatter(const int* __restrict__ ei) {
    int e = blockIdx.x * blockDim.x + threadIdx.x;
    if (e < N_EDGES) {
        int s = ei[e];
        int d = ei[N_EDGES + e];
        if ((unsigned)d < (unsigned)N_NODES && (unsigned)s < (unsigned)N_NODES) {
            int pos = atomicAdd(&g_cursor[d], 1);
            g_csr_src[pos] = s;
        }
    }
}

// ---------------- layer-1 dense transforms ----------------------------------
// y1l[n] = x[n] @ W1l ; y1r[n] = x[n] @ W1r + b1   (thread per node)
__global__ void k_transform1(const float* __restrict__ x,
                             const float* __restrict__ W1l,
                             const float* __restrict__ W1r,
                             const float* __restrict__ b1) {
    __shared__ float sWl[D_IN * D_HID];
    __shared__ float sWr[D_IN * D_HID];
    __shared__ float sb[D_HID];
    for (int i = threadIdx.x; i < D_IN * D_HID; i += blockDim.x) {
        sWl[i] = W1l[i];
        sWr[i] = W1r[i];
    }
    if (threadIdx.x < D_HID) sb[threadIdx.x] = b1[threadIdx.x];
    __syncthreads();

    int n = blockIdx.x * blockDim.x + threadIdx.x;
    if (n >= N_NODES) return;

    float accL[D_HID];
    float accR[D_HID];
#pragma unroll
    for (int j = 0; j < D_HID; j++) { accL[j] = 0.0f; accR[j] = sb[j]; }

    const float4* xr = reinterpret_cast<const float4*>(x + (size_t)n * D_IN);
#pragma unroll 4
    for (int kq = 0; kq < D_IN / 4; kq++) {
        float4 xv4 = xr[kq];
        float xv[4] = {xv4.x, xv4.y, xv4.z, xv4.w};
#pragma unroll
        for (int ki = 0; ki < 4; ki++) {
            int k = kq * 4 + ki;
#pragma unroll
            for (int j = 0; j < D_HID; j++) {
                accL[j] = fmaf(xv[ki], sWl[k * D_HID + j], accL[j]);
                accR[j] = fmaf(xv[ki], sWr[k * D_HID + j], accR[j]);
            }
        }
    }
    float4* outL = reinterpret_cast<float4*>(g_y1l + (size_t)n * D_HID);
    float4* outR = reinterpret_cast<float4*>(g_y1r + (size_t)n * D_HID);
#pragma unroll
    for (int jj = 0; jj < D_HID / 4; jj++) {
        outL[jj] = make_float4(accL[4 * jj], accL[4 * jj + 1], accL[4 * jj + 2], accL[4 * jj + 3]);
        outR[jj] = make_float4(accR[4 * jj], accR[4 * jj + 1], accR[4 * jj + 2], accR[4 * jj + 3]);
    }
}

// ---------------- aggregation: warp per node, lane = feature ----------------
// LAYER1: h = relu(mean_agg(y1l) + y1r)
__global__ void k_aggregate1() {
    int warp = (blockIdx.x * blockDim.x + threadIdx.x) >> 5;
    int lane = threadIdx.x & 31;
    if (warp >= N_NODES) return;
    int beg = g_rowptr[warp];
    int end = g_rowptr[warp + 1];
    float acc = 0.0f;
    int e = beg;
    for (; e + 3 < end; e += 4) {
        int s0 = g_csr_src[e + 0];
        int s1 = g_csr_src[e + 1];
        int s2 = g_csr_src[e + 2];
        int s3 = g_csr_src[e + 3];
        float v0 = g_y1l[(size_t)s0 * D_HID + lane];
        float v1 = g_y1l[(size_t)s1 * D_HID + lane];
        float v2 = g_y1l[(size_t)s2 * D_HID + lane];
        float v3 = g_y1l[(size_t)s3 * D_HID + lane];
        acc += (v0 + v1) + (v2 + v3);
    }
    for (; e < end; e++) {
        int s = g_csr_src[e];
        acc += g_y1l[(size_t)s * D_HID + lane];
    }
    float cnt = (float)(end - beg);
    acc /= fmaxf(cnt, 1.0f);
    float v = acc + g_y1r[(size_t)warp * D_HID + lane];
    g_h[(size_t)warp * D_HID + lane] = fmaxf(v, 0.0f);
}

// LAYER2: agg2 = mean_agg(h)
__global__ void k_aggregate2() {
    int warp = (blockIdx.x * blockDim.x + threadIdx.x) >> 5;
    int lane = threadIdx.x & 31;
    if (warp >= N_NODES) return;
    int beg = g_rowptr[warp];
    int end = g_rowptr[warp + 1];
    float acc = 0.0f;
    int e = beg;
    for (; e + 3 < end; e += 4) {
        int s0 = g_csr_src[e + 0];
        int s1 = g_csr_src[e + 1];
        int s2 = g_csr_src[e + 2];
        int s3 = g_csr_src[e + 3];
        float v0 = g_h[(size_t)s0 * D_HID + lane];
        float v1 = g_h[(size_t)s1 * D_HID + lane];
        float v2 = g_h[(size_t)s2 * D_HID + lane];
        float v3 = g_h[(size_t)s3 * D_HID + lane];
        acc += (v0 + v1) + (v2 + v3);
    }
    for (; e < end; e++) {
        int s = g_csr_src[e];
        acc += g_h[(size_t)s * D_HID + lane];
    }
    float cnt = (float)(end - beg);
    g_agg2[(size_t)warp * D_HID + lane] = acc / fmaxf(cnt, 1.0f);
}

// ---------------- output: out = agg2 @ W2l + h @ W2r + b2 (thread per node) -
__global__ void k_out(const float* __restrict__ W2l,
                      const float* __restrict__ W2r,
                      const float* __restrict__ b2,
                      float* __restrict__ out) {
    __shared__ float sWl[D_HID * D_OUT];
    __shared__ float sWr[D_HID * D_OUT];
    __shared__ float sb[D_OUT];
    for (int i = threadIdx.x; i < D_HID * D_OUT; i += blockDim.x) {
        sWl[i] = W2l[i];
        sWr[i] = W2r[i];
    }
    if (threadIdx.x < D_OUT) sb[threadIdx.x] = b2[threadIdx.x];
    __syncthreads();

    int n = blockIdx.x * blockDim.x + threadIdx.x;
    if (n >= N_NODES) return;

    float acc[D_OUT];
#pragma unroll
    for (int j = 0; j < D_OUT; j++) acc[j] = sb[j];

    const float4* ar = reinterpret_cast<const float4*>(g_agg2 + (size_t)n * D_HID);
    const float4* hr = reinterpret_cast<const float4*>(g_h + (size_t)n * D_HID);

#pragma unroll
    for (int kq = 0; kq < D_HID / 4; kq++) {
        float4 a4 = ar[kq];
        float4 h4 = hr[kq];
        float a[4] = {a4.x, a4.y, a4.z, a4.w};
        float hh[4] = {h4.x, h4.y, h4.z, h4.w};
#pragma unroll
        for (int ki = 0; ki < 4; ki++) {
            int k = kq * 4 + ki;
#pragma unroll
            for (int j = 0; j < D_OUT; j++) {
                acc[j] = fmaf(a[ki], sWl[k * D_OUT + j], acc[j]);
                acc[j] = fmaf(hh[ki], sWr[k * D_OUT + j], acc[j]);
            }
        }
    }
    float* o = out + (size_t)n * D_OUT;
#pragma unroll
    for (int j = 0; j < D_OUT; j++) o[j] = acc[j];
}

// ---------------- launch ------------------------------------------------------
extern "C" void kernel_launch(void* const* d_in, const int* in_sizes, int n_in,
                              void* d_out, int out_size) {
    const float* x   = (const float*)d_in[0];
    const int*   ei  = (const int*)d_in[1];   // int32 [2, E] (JAX default x64-off)
    const float* W1l = (const float*)d_in[2];
    const float* b1  = (const float*)d_in[3];
    const float* W1r = (const float*)d_in[4];
    const float* W2l = (const float*)d_in[5];
    const float* b2  = (const float*)d_in[6];
    const float* W2r = (const float*)d_in[7];
    float* out = (float*)d_out;

    // CSR build (reused by both layers)
    k_zero_cnt<<<(N_NODES + 255) / 256, 256>>>();
    k_histogram<<<(N_EDGES + 255) / 256, 256>>>(ei);
    k_scan_a<<<SCAN_NBLK, SCAN_BLK>>>();
    k_scan_b<<<1, 32>>>();
    k_scan_c<<<SCAN_NBLK, SCAN_BLK>>>();
    k_scatter<<<(N_EDGES + 255) / 256, 256>>>(ei);

    // Layer 1: dense transforms, then warp-per-node mean aggregation + relu
    k_transform1<<<(N_NODES + 127) / 128, 128>>>(x, W1l, W1r, b1);
    k_aggregate1<<<(N_NODES * 32 + 255) / 256, 256>>>();

    // Layer 2: aggregate h, then fused output GEMM
    k_aggregate2<<<(N_NODES * 32 + 255) / 256, 256>>>();
    k_out<<<(N_NODES + 127) / 128, 128>>>(W2l, W2r, b2, out);
}